// round 10
// baseline (speedup 1.0000x reference)
#include <cuda_runtime.h>
#include <cstdint>

#define RR 8192
#define NX 32
#define FW_S 4
#define FW_W 12
#define NCHAIN (RR/FW_S)         // 2048 chains, one warp each
#define FWPB 4                   // warps per block
#define FW_BLOCKS (NCHAIN/FWPB)  // 512
#define BW_S 32
#define BW_W 12
#define BW_BLOCKS (RR/BW_S)      // 256
#define BNT 1024
#define PNT 256
#define FULLM 0xffffffffu

// forward products
__device__ float g_Uh [RR*NX*NX];  // [r][j][k] = Uhat[k][j] (valid k<=j; junk below)
__device__ float g_off[RR*NX*NX];  // [r][j][k] = off[j][k]  (row-major off)
__device__ float g_rs [RR*NX];     // rstd diag
__device__ float g_u  [RR*NX];
// prep products
__device__ float g_ZT [RR*NX*NX];  // [r][i][j] = Z[j][i], Z = off @ Linv
__device__ float g_G  [RR*65*NX];  // [r][m][i] = (g @ Linv)[m][i]

// ---------------------------------------------------------------------------
// Forward: one WARP per chain (warm-up 12, chunk 4 -> 2048 chains for
// occupancy). The 32x65 augmented system [M | -ap | w] lives column-per-lane
// in registers; Gaussian elimination via warp shuffles — zero block barriers.
// ---------------------------------------------------------------------------
__global__ __launch_bounds__(128) void fwd_kernel(
    const float* __restrict__ hess, const float* __restrict__ grads,
    const float* __restrict__ Amat, const float* __restrict__ Ptp,
    const float* __restrict__ Pinit)
{
    __shared__ __align__(16) float C1[NX*33];     // Ptp + apat   (columns: [i*33+j])
    __shared__ __align__(16) float C0[NX*33];     // Ptp          (last step, mfac=0)
    __shared__ __align__(16) float Ci[NX*33];     // Pinit + apat (r==0)
    __shared__ __align__(16) float nap[NX*33];    // -ap
    __shared__ __align__(16) float offp[FWPB][NX*36+4];  // per-warp offT, stride 36

    const int tid = threadIdx.x, lane = tid & 31, w = tid >> 5;

    // ---- block init: ap = A@Ptp, apat = ap@A^T, build C0/C1/Ci/nap ----
    {
        float* A_s = offp[0];          // temp (stride 33)
        float* P_s = offp[2];          // temp
        for (int idx = tid; idx < NX*NX; idx += 128) {
            int i = idx >> 5, j = idx & 31;
            A_s[i*33+j] = Amat[idx];
            P_s[i*33+j] = Ptp[idx];
        }
        __syncthreads();
        for (int idx = tid; idx < NX*NX; idx += 128) {  // nap = -(A@P)
            int i = idx >> 5, j = idx & 31;
            float s = 0.f;
            #pragma unroll
            for (int k = 0; k < NX; k++) s += A_s[i*33+k]*P_s[k*33+j];
            nap[i*33+j] = -s;
        }
        __syncthreads();
        for (int idx = tid; idx < NX*NX; idx += 128) {  // apat = ap@A^T; C's
            int i = idx >> 5, j = idx & 31;
            float s = 0.f;
            #pragma unroll
            for (int k = 0; k < NX; k++) s -= nap[i*33+k]*A_s[j*33+k];
            const float P = P_s[i*33+j];
            C1[i*33+j] = P + s;
            C0[i*33+j] = P;
            Ci[i*33+j] = Pinit[idx] + s;
        }
        __syncthreads();
    }

    const int chain = blockIdx.x*FWPB + w;
    const int rmain = chain*FW_S;
    int r0 = rmain - FW_W; if (r0 < 0) r0 = 0;
    const int nsteps = rmain + FW_S - r0;
    float* op = offp[w];

    float a[NX], b[NX], rsd[NX], offr[NX], hp[NX];
    float gv, wv, uacc = 0.f;

    #pragma unroll
    for (int k = 0; k < NX; k++) { offr[k] = 0.f; op[k*36+lane] = 0.f; }
    __syncwarp();

    #pragma unroll
    for (int i = 0; i < NX; i++) hp[i] = hess[(size_t)r0*1024 + i*32 + lane];
    gv = grads[r0*NX + lane];

    for (int step = 0; step < nsteps; step++) {
        const int r = r0 + step;
        const float* Cp = (r == 0) ? Ci : ((r == RR-1) ? C0 : C1);

        // ---- build: a = C + hess - off^T off   (col of M), b = -ap col ----
        #pragma unroll
        for (int i = 0; i < NX; i++) a[i] = Cp[i*33+lane] + hp[i];
        #pragma unroll
        for (int k = 0; k < NX; k++) {
            const float ok = offr[k];
            #pragma unroll
            for (int i4 = 0; i4 < NX; i4 += 4) {
                const float4 v = *(const float4*)&op[k*36 + i4];
                a[i4]   -= v.x*ok; a[i4+1] -= v.y*ok;
                a[i4+2] -= v.z*ok; a[i4+3] -= v.w*ok;
            }
        }
        #pragma unroll
        for (int i = 0; i < NX; i++) b[i] = nap[i*33+lane];
        wv = gv - uacc;   // w[lane] = grad[lane] - u . off[lane][:]

        if (step + 1 < nsteps) {   // prefetch next hess/grad under elimination
            #pragma unroll
            for (int i = 0; i < NX; i++) hp[i] = hess[(size_t)(r+1)*1024 + i*32 + lane];
            gv = grads[(r+1)*NX + lane];
        }

        // ---- shuffle elimination (no barriers, no per-update multiply) ----
        float dmine = 1.f;
        #pragma unroll
        for (int k = 0; k < NX; k++) {
            const float dk = __shfl_sync(FULLM, a[k], k);
            rsd[k] = dk;
            dmine = (lane == k) ? dk : dmine;
            const float invd = __frcp_rn(dk);
            const float ak_s = a[k]*invd;   // lane-local scaled pivot row entries
            const float bk_s = b[k]*invd;
            #pragma unroll
            for (int i = k+1; i < NX; i++) {
                const float t = __shfl_sync(FULLM, a[i], k);
                a[i] -= t*ak_s;
                b[i] -= t*bk_s;
            }
        }
        #pragma unroll
        for (int k = 0; k < NX; k++) rsd[k] = __frsqrt_rn(rsd[k]);
        const float rsmine = __frsqrt_rn(dmine);

        // ---- eliminate w: t_ik = Uhat[k][i]*invd_k = a[k]*rs_k^2 (local) ----
        #pragma unroll
        for (int k = 0; k < NX; k++) {
            const float wk = __shfl_sync(FULLM, wv, k);
            const float t = (lane > k) ? a[k]*rsd[k]*rsd[k] : 0.f;
            wv -= t*wk;
        }

        // ---- extraction: off row, u-dot for next w, smem offT ----
        uacc = 0.f;
        #pragma unroll
        for (int k = 0; k < NX; k++) {
            offr[k] = b[k]*rsd[k];
            const float uk = __shfl_sync(FULLM, wv, k) * rsd[k];
            uacc += uk*offr[k];
            op[k*36+lane] = offr[k];
        }
        __syncwarp();

        if (r >= rmain) {
            const size_t rb = (size_t)r*(NX*NX) + lane*NX;
            #pragma unroll
            for (int k4 = 0; k4 < NX; k4 += 4) {
                *(float4*)&g_off[rb+k4] = make_float4(offr[k4],offr[k4+1],offr[k4+2],offr[k4+3]);
                *(float4*)&g_Uh [rb+k4] = make_float4(a[k4],a[k4+1],a[k4+2],a[k4+3]);
            }
            g_rs[r*NX+lane] = rsmine;
            g_u [r*NX+lane] = wv * rsmine;
        }
    }
}

// ---------------------------------------------------------------------------
// prep: per-r parallel — rebuild L from raw Uhat + rs, invert it (32
// independent column substitutions), then ZT = (off@Linv)^T and G = g@Linv.
// L[i][k] = Uhat[k][i] * rs_k (true Cholesky factor), diag L[k][k] = 1/rs_k,
// Linv diag = rs_k.
// ---------------------------------------------------------------------------
__global__ __launch_bounds__(PNT) void prep_kernel(const float* __restrict__ epsx)
{
    __shared__ float Lh_s[NX*33];     // Lh_s[k*33+i] = L[i][k] (i>k), diag rs_k
    __shared__ float linvT_s[NX*33];  // [j*33+i] = Linv[i][j]
    __shared__ float off_s[NX*33];    // [j*33+k] = off[j][k]
    __shared__ float g_sm[65*NX];
    __shared__ float rs_s[NX];

    const int tid = threadIdx.x;
    const int r = blockIdx.x;
    const size_t rb = (size_t)r * (NX*NX);

    if (tid < NX) rs_s[tid] = g_rs[r*NX + tid];
    {   // off rows
        float4 v = ((const float4*)(g_off + rb))[tid];
        int fi = tid*4, j = fi >> 5, k = fi & 31;
        float* p = &off_s[j*33 + k];
        p[0]=v.x; p[1]=v.y; p[2]=v.z; p[3]=v.w;
    }
    if (tid < NX) g_sm[tid] = g_u[r*NX + tid];
    {
        const float4* es = (const float4*)(epsx + (size_t)r*2048);
        float4* ed = (float4*)&g_sm[NX];
        ed[tid] = es[tid]; ed[tid+PNT] = es[tid+PNT];
    }
    for (int idx = tid; idx < NX*33; idx += PNT) linvT_s[idx] = 0.f;
    __syncthreads();   // rs_s ready

    {   // L[i][k] = Uh[i][k]*rs_k (k<i), rs_k (k==i), 0 else
        float4 v = ((const float4*)(g_Uh + rb))[tid];
        int fi = tid*4, i = fi >> 5, k = fi & 31;
        float vv[4] = {v.x, v.y, v.z, v.w};
        #pragma unroll
        for (int c = 0; c < 4; c++) {
            const int kk = k + c;
            const float rs = rs_s[kk];
            const float val = (kk < i) ? vv[c]*rs : ((kk == i) ? rs : 0.f);
            Lh_s[kk*33 + i] = val;
        }
    }
    __syncthreads();

    // invert L: lane j computes Linv column j (warp 0)
    if (tid < NX) {
        const int j = tid;
        linvT_s[j*33 + j] = Lh_s[j*33 + j];   // 1/L[j][j] = rs_j
        for (int i = 1; i < NX; i++) {
            if (j < i) {
                float s0 = 0.f, s1 = 0.f;
                int k = j;
                for (; k + 1 < i; k += 2) {
                    s0 += Lh_s[k*33 + i]     * linvT_s[j*33 + k];
                    s1 += Lh_s[(k+1)*33 + i] * linvT_s[j*33 + k + 1];
                }
                if (k < i) s0 += Lh_s[k*33 + i] * linvT_s[j*33 + k];
                linvT_s[j*33 + i] = -Lh_s[i*33 + i] * (s0 + s1);
            }
        }
    }
    __syncthreads();

    const int lane = tid & 31, w = tid >> 5;   // 8 warps
    for (int m = w; m < 65; m += 8) {          // G rows
        const float* grow = &g_sm[m*NX];
        float a0 = 0.f, a1 = 0.f;
        #pragma unroll
        for (int k = 0; k < NX; k += 2) {
            a0 += grow[k]   * linvT_s[lane*33 + k];
            a1 += grow[k+1] * linvT_s[lane*33 + k + 1];
        }
        g_G[(size_t)r*2080 + m*NX + lane] = a0 + a1;
    }
    for (int i = w; i < NX; i += 8) {          // ZT rows
        float a0 = 0.f, a1 = 0.f;
        #pragma unroll
        for (int k = 0; k < NX; k += 2) {
            a0 += off_s[lane*33 + k]     * linvT_s[i*33 + k];
            a1 += off_s[lane*33 + k + 1] * linvT_s[i*33 + k + 1];
        }
        g_ZT[rb + i*NX + lane] = a0 + a1;
    }
}

// ---------------------------------------------------------------------------
// Backward: chunked reverse scan (warm-up 12, chunk 32). ONE fused matmul
// per step: vw' = G' - vw @ Z. Depth-2 register prefetch of (ZT, G) tiles.
// ---------------------------------------------------------------------------
__device__ __forceinline__ float4 ldtile(int r, int idx) {
    if (idx < 256) return reinterpret_cast<const float4*>(g_ZT + (size_t)r*1024)[idx];
    return reinterpret_cast<const float4*>(g_G + (size_t)r*2080)[idx - 256];
}

__global__ __launch_bounds__(BNT) void bwd_kernel(float* __restrict__ out)
{
    __shared__ float vw[65*33];
    __shared__ float zt_s[NX*33];
    __shared__ __align__(16) float gbuf[65*NX];

    const int tid = threadIdx.x;
    const int b   = blockIdx.x;
    const int rlow     = b*BW_S;
    const int rmainTop = rlow + BW_S - 1;
    int rtop = rmainTop + BW_W; if (rtop > RR-1) rtop = RR-1;
    const int nsteps = rtop - rlow + 1;

    for (int idx = tid; idx < 65*33; idx += BNT) vw[idx] = 0.f;

    const bool ldr = (tid < 776);   // 776 float4 tiles: 256 (ZT) + 520 (G)
    float4 f0 = ldr ? ldtile(rtop, tid) : make_float4(0,0,0,0);
    float4 f1 = (ldr && nsteps > 1) ? ldtile(rtop-1, tid) : make_float4(0,0,0,0);

    const int lane = tid & 31, w = tid >> 5;   // 32 warps

    for (int step = 0; step < nsteps; step++) {
        const int r = rtop - step;

        if (tid < 256) {
            int fi = tid*4, i = fi >> 5, j = fi & 31;
            float* p = &zt_s[i*33 + j];
            p[0]=f0.x; p[1]=f0.y; p[2]=f0.z; p[3]=f0.w;
        } else if (ldr) {
            reinterpret_cast<float4*>(gbuf)[tid - 256] = f0;
        }
        f0 = f1;
        if (step + 2 < nsteps && ldr) f1 = ldtile(r-2, tid);
        __syncthreads();

        float ztr[NX];
        #pragma unroll
        for (int j = 0; j < NX; j++) ztr[j] = zt_s[lane*33 + j];

        for (int m = w; m < 65; m += 32) {
            float a0 = gbuf[m*NX + lane], a1 = 0.f;
            #pragma unroll
            for (int j = 0; j < NX; j += 2) {
                a0 -= vw[m*33 + j]     * ztr[j];
                a1 += vw[m*33 + j + 1] * ztr[j+1];
            }
            vw[m*33 + lane] = a0 - a1;
        }
        __syncthreads();

        if (r <= rmainTop) {
            float* orow = out + (size_t)r * 2048;
            const int m = tid >> 5, i = tid & 31;
            orow[tid] = vw[i] + vw[(m+1)*33 + i];
            const int idx2 = tid + BNT;
            const int m2 = idx2 >> 5, i2 = idx2 & 31;
            orow[idx2] = vw[i2] + vw[(m2+1)*33 + i2];
        }
    }
}

extern "C" void kernel_launch(void* const* d_in, const int* in_sizes, int n_in,
                              void* d_out, int out_size) {
    const float* hess  = (const float*)d_in[0];   // (8192,32,32)
    const float* grads = (const float*)d_in[1];   // (8192,1,32)
    const float* Amat  = (const float*)d_in[2];   // (32,32)
    const float* Ptp   = (const float*)d_in[3];   // (32,32)
    const float* Pinit = (const float*)d_in[4];   // (32,32)
    const float* epsx  = (const float*)d_in[5];   // (8192,64,32)
    float* out = (float*)d_out;                   // (8192,64,32)
    (void)in_sizes; (void)n_in; (void)out_size;

    fwd_kernel<<<FW_BLOCKS, 128>>>(hess, grads, Amat, Ptp, Pinit);
    prep_kernel<<<RR, PNT>>>(epsx);
    bwd_kernel<<<BW_BLOCKS, BNT>>>(out);
}

// round 11
// speedup vs baseline: 1.2645x; 1.2645x over previous
#include <cuda_runtime.h>
#include <cstdint>

#define RR 8192
#define NX 32
#define FW_S 8
#define FW_W 12
#define NCHAIN (RR/FW_S)         // 1024 chains, one warp each
#define FWPB 4                   // warps per block
#define FW_BLOCKS (NCHAIN/FWPB)  // 256
#define BW_S 32
#define BW_W 12
#define BW_BLOCKS (RR/BW_S)      // 256
#define BNT 1024
#define PNT 256
#define FULLM 0xffffffffu

// forward products
__device__ float g_Uh [RR*NX*NX];  // [r][j][k] = Uhat[k][j] (valid k<=j; junk below)
__device__ float g_off[RR*NX*NX];  // [r][j][k] = off[j][k]  (row-major off)
__device__ float g_rs [RR*NX];     // rstd diag
__device__ float g_u  [RR*NX];
// prep products
__device__ float g_ZT [RR*NX*NX];  // [r][i][j] = Z[j][i], Z = off @ Linv
__device__ float g_G  [RR*65*NX];  // [r][m][i] = (g @ Linv)[m][i]

// ---------------------------------------------------------------------------
// Forward: one WARP per chain (warm-up 12, chunk 8 -> 1024 chains; best
// measured step-count/occupancy trade). The 32x65 augmented system
// [M | -ap | w] lives column-per-lane in registers; Gaussian elimination via
// warp shuffles — zero block barriers.
// ---------------------------------------------------------------------------
__global__ __launch_bounds__(128) void fwd_kernel(
    const float* __restrict__ hess, const float* __restrict__ grads,
    const float* __restrict__ Amat, const float* __restrict__ Ptp,
    const float* __restrict__ Pinit)
{
    __shared__ __align__(16) float C1[NX*33];     // Ptp + apat   (columns: [i*33+j])
    __shared__ __align__(16) float C0[NX*33];     // Ptp          (last step, mfac=0)
    __shared__ __align__(16) float Ci[NX*33];     // Pinit + apat (r==0)
    __shared__ __align__(16) float nap[NX*33];    // -ap
    __shared__ __align__(16) float offp[FWPB][NX*36+4];  // per-warp offT, stride 36

    const int tid = threadIdx.x, lane = tid & 31, w = tid >> 5;

    // ---- block init: ap = A@Ptp, apat = ap@A^T, build C0/C1/Ci/nap ----
    {
        float* A_s = offp[0];          // temp (stride 33)
        float* P_s = offp[2];          // temp
        for (int idx = tid; idx < NX*NX; idx += 128) {
            int i = idx >> 5, j = idx & 31;
            A_s[i*33+j] = Amat[idx];
            P_s[i*33+j] = Ptp[idx];
        }
        __syncthreads();
        for (int idx = tid; idx < NX*NX; idx += 128) {  // nap = -(A@P)
            int i = idx >> 5, j = idx & 31;
            float s = 0.f;
            #pragma unroll
            for (int k = 0; k < NX; k++) s += A_s[i*33+k]*P_s[k*33+j];
            nap[i*33+j] = -s;
        }
        __syncthreads();
        for (int idx = tid; idx < NX*NX; idx += 128) {  // apat = ap@A^T; C's
            int i = idx >> 5, j = idx & 31;
            float s = 0.f;
            #pragma unroll
            for (int k = 0; k < NX; k++) s -= nap[i*33+k]*A_s[j*33+k];
            const float P = P_s[i*33+j];
            C1[i*33+j] = P + s;
            C0[i*33+j] = P;
            Ci[i*33+j] = Pinit[idx] + s;
        }
        __syncthreads();
    }

    const int chain = blockIdx.x*FWPB + w;
    const int rmain = chain*FW_S;
    int r0 = rmain - FW_W; if (r0 < 0) r0 = 0;
    const int nsteps = rmain + FW_S - r0;
    float* op = offp[w];

    float a[NX], b[NX], rsd[NX], offr[NX], hp[NX];
    float gv, wv, uacc = 0.f;

    #pragma unroll
    for (int k = 0; k < NX; k++) { offr[k] = 0.f; op[k*36+lane] = 0.f; }
    __syncwarp();

    #pragma unroll
    for (int i = 0; i < NX; i++) hp[i] = hess[(size_t)r0*1024 + i*32 + lane];
    gv = grads[r0*NX + lane];

    for (int step = 0; step < nsteps; step++) {
        const int r = r0 + step;
        const float* Cp = (r == 0) ? Ci : ((r == RR-1) ? C0 : C1);

        // ---- build: a = C + hess - off^T off   (col of M), b = -ap col ----
        #pragma unroll
        for (int i = 0; i < NX; i++) a[i] = Cp[i*33+lane] + hp[i];
        #pragma unroll
        for (int k = 0; k < NX; k++) {
            const float ok = offr[k];
            #pragma unroll
            for (int i4 = 0; i4 < NX; i4 += 4) {
                const float4 v = *(const float4*)&op[k*36 + i4];
                a[i4]   -= v.x*ok; a[i4+1] -= v.y*ok;
                a[i4+2] -= v.z*ok; a[i4+3] -= v.w*ok;
            }
        }
        #pragma unroll
        for (int i = 0; i < NX; i++) b[i] = nap[i*33+lane];
        wv = gv - uacc;   // w[lane] = grad[lane] - u . off[lane][:]

        if (step + 1 < nsteps) {   // prefetch next hess/grad under elimination
            #pragma unroll
            for (int i = 0; i < NX; i++) hp[i] = hess[(size_t)(r+1)*1024 + i*32 + lane];
            gv = grads[(r+1)*NX + lane];
        }

        // ---- shuffle elimination (no barriers, no per-update multiply) ----
        float dmine = 1.f;
        #pragma unroll
        for (int k = 0; k < NX; k++) {
            const float dk = __shfl_sync(FULLM, a[k], k);
            rsd[k] = dk;
            dmine = (lane == k) ? dk : dmine;
            const float invd = __frcp_rn(dk);
            const float ak_s = a[k]*invd;   // lane-local scaled pivot row entries
            const float bk_s = b[k]*invd;
            #pragma unroll
            for (int i = k+1; i < NX; i++) {
                const float t = __shfl_sync(FULLM, a[i], k);
                a[i] -= t*ak_s;
                b[i] -= t*bk_s;
            }
        }
        #pragma unroll
        for (int k = 0; k < NX; k++) rsd[k] = __frsqrt_rn(rsd[k]);
        const float rsmine = __frsqrt_rn(dmine);

        // ---- eliminate w: t_ik = Uhat[k][i]*invd_k = a[k]*rs_k^2 (local) ----
        #pragma unroll
        for (int k = 0; k < NX; k++) {
            const float wk = __shfl_sync(FULLM, wv, k);
            const float t = (lane > k) ? a[k]*rsd[k]*rsd[k] : 0.f;
            wv -= t*wk;
        }

        // ---- extraction: off row, u-dot for next w, smem offT ----
        uacc = 0.f;
        #pragma unroll
        for (int k = 0; k < NX; k++) {
            offr[k] = b[k]*rsd[k];
            const float uk = __shfl_sync(FULLM, wv, k) * rsd[k];
            uacc += uk*offr[k];
            op[k*36+lane] = offr[k];
        }
        __syncwarp();

        if (r >= rmain) {
            const size_t rb = (size_t)r*(NX*NX) + lane*NX;
            #pragma unroll
            for (int k4 = 0; k4 < NX; k4 += 4) {
                *(float4*)&g_off[rb+k4] = make_float4(offr[k4],offr[k4+1],offr[k4+2],offr[k4+3]);
                *(float4*)&g_Uh [rb+k4] = make_float4(a[k4],a[k4+1],a[k4+2],a[k4+3]);
            }
            g_rs[r*NX+lane] = rsmine;
            g_u [r*NX+lane] = wv * rsmine;
        }
    }
}

// ---------------------------------------------------------------------------
// prep: per-r parallel — rebuild L from raw Uhat + rs, invert it (32
// independent column substitutions), then ZT = (off@Linv)^T and G = g@Linv.
// L[i][k] = Uhat[k][i] * rs_k (true Cholesky factor), diag L[k][k] = 1/rs_k,
// Linv diag = rs_k.
// ---------------------------------------------------------------------------
__global__ __launch_bounds__(PNT) void prep_kernel(const float* __restrict__ epsx)
{
    __shared__ float Lh_s[NX*33];     // Lh_s[k*33+i] = L[i][k] (i>k), diag rs_k
    __shared__ float linvT_s[NX*33];  // [j*33+i] = Linv[i][j]
    __shared__ float off_s[NX*33];    // [j*33+k] = off[j][k]
    __shared__ float g_sm[65*NX];
    __shared__ float rs_s[NX];

    const int tid = threadIdx.x;
    const int r = blockIdx.x;
    const size_t rb = (size_t)r * (NX*NX);

    if (tid < NX) rs_s[tid] = g_rs[r*NX + tid];
    {   // off rows
        float4 v = ((const float4*)(g_off + rb))[tid];
        int fi = tid*4, j = fi >> 5, k = fi & 31;
        float* p = &off_s[j*33 + k];
        p[0]=v.x; p[1]=v.y; p[2]=v.z; p[3]=v.w;
    }
    if (tid < NX) g_sm[tid] = g_u[r*NX + tid];
    {
        const float4* es = (const float4*)(epsx + (size_t)r*2048);
        float4* ed = (float4*)&g_sm[NX];
        ed[tid] = es[tid]; ed[tid+PNT] = es[tid+PNT];
    }
    for (int idx = tid; idx < NX*33; idx += PNT) linvT_s[idx] = 0.f;
    __syncthreads();   // rs_s ready

    {   // L[i][k] = Uh[i][k]*rs_k (k<i), rs_k (k==i), 0 else
        float4 v = ((const float4*)(g_Uh + rb))[tid];
        int fi = tid*4, i = fi >> 5, k = fi & 31;
        float vv[4] = {v.x, v.y, v.z, v.w};
        #pragma unroll
        for (int c = 0; c < 4; c++) {
            const int kk = k + c;
            const float rs = rs_s[kk];
            const float val = (kk < i) ? vv[c]*rs : ((kk == i) ? rs : 0.f);
            Lh_s[kk*33 + i] = val;
        }
    }
    __syncthreads();

    // invert L: lane j computes Linv column j (warp 0)
    if (tid < NX) {
        const int j = tid;
        linvT_s[j*33 + j] = Lh_s[j*33 + j];   // 1/L[j][j] = rs_j
        for (int i = 1; i < NX; i++) {
            if (j < i) {
                float s0 = 0.f, s1 = 0.f;
                int k = j;
                for (; k + 1 < i; k += 2) {
                    s0 += Lh_s[k*33 + i]     * linvT_s[j*33 + k];
                    s1 += Lh_s[(k+1)*33 + i] * linvT_s[j*33 + k + 1];
                }
                if (k < i) s0 += Lh_s[k*33 + i] * linvT_s[j*33 + k];
                linvT_s[j*33 + i] = -Lh_s[i*33 + i] * (s0 + s1);
            }
        }
    }
    __syncthreads();

    const int lane = tid & 31, w = tid >> 5;   // 8 warps
    for (int m = w; m < 65; m += 8) {          // G rows
        const float* grow = &g_sm[m*NX];
        float a0 = 0.f, a1 = 0.f;
        #pragma unroll
        for (int k = 0; k < NX; k += 2) {
            a0 += grow[k]   * linvT_s[lane*33 + k];
            a1 += grow[k+1] * linvT_s[lane*33 + k + 1];
        }
        g_G[(size_t)r*2080 + m*NX + lane] = a0 + a1;
    }
    for (int i = w; i < NX; i += 8) {          // ZT rows
        float a0 = 0.f, a1 = 0.f;
        #pragma unroll
        for (int k = 0; k < NX; k += 2) {
            a0 += off_s[lane*33 + k]     * linvT_s[i*33 + k];
            a1 += off_s[lane*33 + k + 1] * linvT_s[i*33 + k + 1];
        }
        g_ZT[rb + i*NX + lane] = a0 + a1;
    }
}

// ---------------------------------------------------------------------------
// Backward: chunked reverse scan (warm-up 12, chunk 32). ONE fused matmul
// per step: vw' = G' - vw @ Z. Depth-2 register prefetch of (ZT, G) tiles.
// ---------------------------------------------------------------------------
__device__ __forceinline__ float4 ldtile(int r, int idx) {
    if (idx < 256) return reinterpret_cast<const float4*>(g_ZT + (size_t)r*1024)[idx];
    return reinterpret_cast<const float4*>(g_G + (size_t)r*2080)[idx - 256];
}

__global__ __launch_bounds__(BNT) void bwd_kernel(float* __restrict__ out)
{
    __shared__ float vw[65*33];
    __shared__ float zt_s[NX*33];
    __shared__ __align__(16) float gbuf[65*NX];

    const int tid = threadIdx.x;
    const int b   = blockIdx.x;
    const int rlow     = b*BW_S;
    const int rmainTop = rlow + BW_S - 1;
    int rtop = rmainTop + BW_W; if (rtop > RR-1) rtop = RR-1;
    const int nsteps = rtop - rlow + 1;

    for (int idx = tid; idx < 65*33; idx += BNT) vw[idx] = 0.f;

    const bool ldr = (tid < 776);   // 776 float4 tiles: 256 (ZT) + 520 (G)
    float4 f0 = ldr ? ldtile(rtop, tid) : make_float4(0,0,0,0);
    float4 f1 = (ldr && nsteps > 1) ? ldtile(rtop-1, tid) : make_float4(0,0,0,0);

    const int lane = tid & 31, w = tid >> 5;   // 32 warps

    for (int step = 0; step < nsteps; step++) {
        const int r = rtop - step;

        if (tid < 256) {
            int fi = tid*4, i = fi >> 5, j = fi & 31;
            float* p = &zt_s[i*33 + j];
            p[0]=f0.x; p[1]=f0.y; p[2]=f0.z; p[3]=f0.w;
        } else if (ldr) {
            reinterpret_cast<float4*>(gbuf)[tid - 256] = f0;
        }
        f0 = f1;
        if (step + 2 < nsteps && ldr) f1 = ldtile(r-2, tid);
        __syncthreads();

        float ztr[NX];
        #pragma unroll
        for (int j = 0; j < NX; j++) ztr[j] = zt_s[lane*33 + j];

        for (int m = w; m < 65; m += 32) {
            float a0 = gbuf[m*NX + lane], a1 = 0.f;
            #pragma unroll
            for (int j = 0; j < NX; j += 2) {
                a0 -= vw[m*33 + j]     * ztr[j];
                a1 += vw[m*33 + j + 1] * ztr[j+1];
            }
            vw[m*33 + lane] = a0 - a1;
        }
        __syncthreads();

        if (r <= rmainTop) {
            float* orow = out + (size_t)r * 2048;
            const int m = tid >> 5, i = tid & 31;
            orow[tid] = vw[i] + vw[(m+1)*33 + i];
            const int idx2 = tid + BNT;
            const int m2 = idx2 >> 5, i2 = idx2 & 31;
            orow[idx2] = vw[i2] + vw[(m2+1)*33 + i2];
        }
    }
}

extern "C" void kernel_launch(void* const* d_in, const int* in_sizes, int n_in,
                              void* d_out, int out_size) {
    const float* hess  = (const float*)d_in[0];   // (8192,32,32)
    const float* grads = (const float*)d_in[1];   // (8192,1,32)
    const float* Amat  = (const float*)d_in[2];   // (32,32)
    const float* Ptp   = (const float*)d_in[3];   // (32,32)
    const float* Pinit = (const float*)d_in[4];   // (32,32)
    const float* epsx  = (const float*)d_in[5];   // (8192,64,32)
    float* out = (float*)d_out;                   // (8192,64,32)
    (void)in_sizes; (void)n_in; (void)out_size;

    fwd_kernel<<<FW_BLOCKS, 128>>>(hess, grads, Amat, Ptp, Pinit);
    prep_kernel<<<RR, PNT>>>(epsx);
    bwd_kernel<<<BW_BLOCKS, BNT>>>(out);
}

// round 12
// speedup vs baseline: 1.4218x; 1.1244x over previous
#include <cuda_runtime.h>
#include <cstdint>

#define RR 8192
#define NX 32
#define FW_S 8
#define FW_W 8
#define NCHAIN (RR/FW_S)         // 1024 chains, one warp each
#define FWPB 4                   // warps per block
#define FW_BLOCKS (NCHAIN/FWPB)  // 256
#define BW_S 16
#define BW_W 8
#define BW_BLOCKS (RR/BW_S)      // 512
#define BNT 512
#define PNT 256
#define FULLM 0xffffffffu

// forward products
__device__ float g_Uh [RR*NX*NX];  // [r][j][k] = Uhat[k][j] (valid k<=j; junk below)
__device__ float g_off[RR*NX*NX];  // [r][j][k] = off[j][k]  (row-major off)
__device__ float g_rs [RR*NX];     // rstd diag
__device__ float g_u  [RR*NX];
// prep products
__device__ float g_ZT [RR*NX*NX];  // [r][i][j] = Z[j][i], Z = off @ Linv
__device__ float g_G  [RR*65*NX];  // [r][m][i] = (g @ Linv)[m][i]

// ---------------------------------------------------------------------------
// Forward: one WARP per chain (warm-up 8, chunk 8 -> 1024 chains). The 32x65
// augmented system [M | -ap | w] lives column-per-lane in registers; Gaussian
// elimination via warp shuffles — zero block barriers.
// ---------------------------------------------------------------------------
__global__ __launch_bounds__(128) void fwd_kernel(
    const float* __restrict__ hess, const float* __restrict__ grads,
    const float* __restrict__ Amat, const float* __restrict__ Ptp,
    const float* __restrict__ Pinit)
{
    __shared__ __align__(16) float C1[NX*33];     // Ptp + apat   (columns: [i*33+j])
    __shared__ __align__(16) float C0[NX*33];     // Ptp          (last step, mfac=0)
    __shared__ __align__(16) float Ci[NX*33];     // Pinit + apat (r==0)
    __shared__ __align__(16) float nap[NX*33];    // -ap
    __shared__ __align__(16) float offp[FWPB][NX*36+4];  // per-warp offT, stride 36

    const int tid = threadIdx.x, lane = tid & 31, w = tid >> 5;

    // ---- block init: ap = A@Ptp, apat = ap@A^T, build C0/C1/Ci/nap ----
    {
        float* A_s = offp[0];          // temp (stride 33)
        float* P_s = offp[2];          // temp
        for (int idx = tid; idx < NX*NX; idx += 128) {
            int i = idx >> 5, j = idx & 31;
            A_s[i*33+j] = Amat[idx];
            P_s[i*33+j] = Ptp[idx];
        }
        __syncthreads();
        for (int idx = tid; idx < NX*NX; idx += 128) {  // nap = -(A@P)
            int i = idx >> 5, j = idx & 31;
            float s = 0.f;
            #pragma unroll
            for (int k = 0; k < NX; k++) s += A_s[i*33+k]*P_s[k*33+j];
            nap[i*33+j] = -s;
        }
        __syncthreads();
        for (int idx = tid; idx < NX*NX; idx += 128) {  // apat = ap@A^T; C's
            int i = idx >> 5, j = idx & 31;
            float s = 0.f;
            #pragma unroll
            for (int k = 0; k < NX; k++) s -= nap[i*33+k]*A_s[j*33+k];
            const float P = P_s[i*33+j];
            C1[i*33+j] = P + s;
            C0[i*33+j] = P;
            Ci[i*33+j] = Pinit[idx] + s;
        }
        __syncthreads();
    }

    const int chain = blockIdx.x*FWPB + w;
    const int rmain = chain*FW_S;
    int r0 = rmain - FW_W; if (r0 < 0) r0 = 0;
    const int nsteps = rmain + FW_S - r0;
    float* op = offp[w];

    float a[NX], b[NX], rsd[NX], offr[NX], hp[NX];
    float gv, wv, uacc = 0.f;

    #pragma unroll
    for (int k = 0; k < NX; k++) { offr[k] = 0.f; op[k*36+lane] = 0.f; }
    __syncwarp();

    #pragma unroll
    for (int i = 0; i < NX; i++) hp[i] = hess[(size_t)r0*1024 + i*32 + lane];
    gv = grads[r0*NX + lane];

    for (int step = 0; step < nsteps; step++) {
        const int r = r0 + step;
        const float* Cp = (r == 0) ? Ci : ((r == RR-1) ? C0 : C1);

        // ---- build: a = C + hess - off^T off   (col of M), b = -ap col ----
        #pragma unroll
        for (int i = 0; i < NX; i++) a[i] = Cp[i*33+lane] + hp[i];
        #pragma unroll
        for (int k = 0; k < NX; k++) {
            const float ok = offr[k];
            #pragma unroll
            for (int i4 = 0; i4 < NX; i4 += 4) {
                const float4 v = *(const float4*)&op[k*36 + i4];
                a[i4]   -= v.x*ok; a[i4+1] -= v.y*ok;
                a[i4+2] -= v.z*ok; a[i4+3] -= v.w*ok;
            }
        }
        #pragma unroll
        for (int i = 0; i < NX; i++) b[i] = nap[i*33+lane];
        wv = gv - uacc;   // w[lane] = grad[lane] - u . off[lane][:]

        if (step + 1 < nsteps) {   // prefetch next hess/grad under elimination
            #pragma unroll
            for (int i = 0; i < NX; i++) hp[i] = hess[(size_t)(r+1)*1024 + i*32 + lane];
            gv = grads[(r+1)*NX + lane];
        }

        // ---- shuffle elimination (no barriers, no per-update multiply) ----
        float dmine = 1.f;
        #pragma unroll
        for (int k = 0; k < NX; k++) {
            const float dk = __shfl_sync(FULLM, a[k], k);
            rsd[k] = dk;
            dmine = (lane == k) ? dk : dmine;
            const float invd = __frcp_rn(dk);
            const float ak_s = a[k]*invd;   // lane-local scaled pivot row entries
            const float bk_s = b[k]*invd;
            #pragma unroll
            for (int i = k+1; i < NX; i++) {
                const float t = __shfl_sync(FULLM, a[i], k);
                a[i] -= t*ak_s;
                b[i] -= t*bk_s;
            }
        }
        #pragma unroll
        for (int k = 0; k < NX; k++) rsd[k] = __frsqrt_rn(rsd[k]);
        const float rsmine = __frsqrt_rn(dmine);

        // ---- eliminate w: t_ik = Uhat[k][i]*invd_k = a[k]*rs_k^2 (local) ----
        #pragma unroll
        for (int k = 0; k < NX; k++) {
            const float wk = __shfl_sync(FULLM, wv, k);
            const float t = (lane > k) ? a[k]*rsd[k]*rsd[k] : 0.f;
            wv -= t*wk;
        }

        // ---- extraction: off row, u-dot for next w, smem offT ----
        uacc = 0.f;
        #pragma unroll
        for (int k = 0; k < NX; k++) {
            offr[k] = b[k]*rsd[k];
            const float uk = __shfl_sync(FULLM, wv, k) * rsd[k];
            uacc += uk*offr[k];
            op[k*36+lane] = offr[k];
        }
        __syncwarp();

        if (r >= rmain) {
            const size_t rb = (size_t)r*(NX*NX) + lane*NX;
            #pragma unroll
            for (int k4 = 0; k4 < NX; k4 += 4) {
                *(float4*)&g_off[rb+k4] = make_float4(offr[k4],offr[k4+1],offr[k4+2],offr[k4+3]);
                *(float4*)&g_Uh [rb+k4] = make_float4(a[k4],a[k4+1],a[k4+2],a[k4+3]);
            }
            g_rs[r*NX+lane] = rsmine;
            g_u [r*NX+lane] = wv * rsmine;
        }
    }
}

// ---------------------------------------------------------------------------
// prep: per-r parallel — rebuild L from raw Uhat + rs, invert it (32
// independent column substitutions), then ZT = (off@Linv)^T and G = g@Linv.
// ---------------------------------------------------------------------------
__global__ __launch_bounds__(PNT) void prep_kernel(const float* __restrict__ epsx)
{
    __shared__ float Lh_s[NX*33];     // Lh_s[k*33+i] = L[i][k] (i>k), diag rs_k
    __shared__ float linvT_s[NX*33];  // [j*33+i] = Linv[i][j]
    __shared__ float off_s[NX*33];    // [j*33+k] = off[j][k]
    __shared__ float g_sm[65*NX];
    __shared__ float rs_s[NX];

    const int tid = threadIdx.x;
    const int r = blockIdx.x;
    const size_t rb = (size_t)r * (NX*NX);

    if (tid < NX) rs_s[tid] = g_rs[r*NX + tid];
    {   // off rows
        float4 v = ((const float4*)(g_off + rb))[tid];
        int fi = tid*4, j = fi >> 5, k = fi & 31;
        float* p = &off_s[j*33 + k];
        p[0]=v.x; p[1]=v.y; p[2]=v.z; p[3]=v.w;
    }
    if (tid < NX) g_sm[tid] = g_u[r*NX + tid];
    {
        const float4* es = (const float4*)(epsx + (size_t)r*2048);
        float4* ed = (float4*)&g_sm[NX];
        ed[tid] = es[tid]; ed[tid+PNT] = es[tid+PNT];
    }
    for (int idx = tid; idx < NX*33; idx += PNT) linvT_s[idx] = 0.f;
    __syncthreads();   // rs_s ready

    {   // L[i][k] = Uh[i][k]*rs_k (k<i), rs_k (k==i), 0 else
        float4 v = ((const float4*)(g_Uh + rb))[tid];
        int fi = tid*4, i = fi >> 5, k = fi & 31;
        float vv[4] = {v.x, v.y, v.z, v.w};
        #pragma unroll
        for (int c = 0; c < 4; c++) {
            const int kk = k + c;
            const float rs = rs_s[kk];
            const float val = (kk < i) ? vv[c]*rs : ((kk == i) ? rs : 0.f);
            Lh_s[kk*33 + i] = val;
        }
    }
    __syncthreads();

    // invert L: lane j computes Linv column j (warp 0)
    if (tid < NX) {
        const int j = tid;
        linvT_s[j*33 + j] = Lh_s[j*33 + j];   // 1/L[j][j] = rs_j
        for (int i = 1; i < NX; i++) {
            if (j < i) {
                float s0 = 0.f, s1 = 0.f;
                int k = j;
                for (; k + 1 < i; k += 2) {
                    s0 += Lh_s[k*33 + i]     * linvT_s[j*33 + k];
                    s1 += Lh_s[(k+1)*33 + i] * linvT_s[j*33 + k + 1];
                }
                if (k < i) s0 += Lh_s[k*33 + i] * linvT_s[j*33 + k];
                linvT_s[j*33 + i] = -Lh_s[i*33 + i] * (s0 + s1);
            }
        }
    }
    __syncthreads();

    const int lane = tid & 31, w = tid >> 5;   // 8 warps
    for (int m = w; m < 65; m += 8) {          // G rows
        const float* grow = &g_sm[m*NX];
        float a0 = 0.f, a1 = 0.f;
        #pragma unroll
        for (int k = 0; k < NX; k += 2) {
            a0 += grow[k]   * linvT_s[lane*33 + k];
            a1 += grow[k+1] * linvT_s[lane*33 + k + 1];
        }
        g_G[(size_t)r*2080 + m*NX + lane] = a0 + a1;
    }
    for (int i = w; i < NX; i += 8) {          // ZT rows
        float a0 = 0.f, a1 = 0.f;
        #pragma unroll
        for (int k = 0; k < NX; k += 2) {
            a0 += off_s[lane*33 + k]     * linvT_s[i*33 + k];
            a1 += off_s[lane*33 + k + 1] * linvT_s[i*33 + k + 1];
        }
        g_ZT[rb + i*NX + lane] = a0 + a1;
    }
}

// ---------------------------------------------------------------------------
// Backward: chunked reverse scan (warm-up 8, chunk 16 -> 512 blocks of 512
// threads; 128-reg budget keeps the per-lane Z row in registers, no spills).
// ONE fused matmul per step: vw' = G' - vw @ Z.
// ---------------------------------------------------------------------------
__device__ __forceinline__ float4 ldtile(int r, int idx) {
    if (idx < 256) return reinterpret_cast<const float4*>(g_ZT + (size_t)r*1024)[idx];
    return reinterpret_cast<const float4*>(g_G + (size_t)r*2080)[idx - 256];
}

__global__ __launch_bounds__(BNT) void bwd_kernel(float* __restrict__ out)
{
    __shared__ float vw[65*33];
    __shared__ float zt_s[NX*33];
    __shared__ __align__(16) float gbuf[65*NX];

    const int tid = threadIdx.x;
    const int b   = blockIdx.x;
    const int rlow     = b*BW_S;
    const int rmainTop = rlow + BW_S - 1;
    int rtop = rmainTop + BW_W; if (rtop > RR-1) rtop = RR-1;
    const int nsteps = rtop - rlow + 1;

    for (int idx = tid; idx < 65*33; idx += BNT) vw[idx] = 0.f;

    // 776 float4 tiles per step: 256 (ZT) + 520 (G); 2 tiles per thread
    const bool ld2 = (tid < 264);
    float4 f0 = ldtile(rtop, tid);
    float4 f1 = ld2 ? ldtile(rtop, tid + BNT) : make_float4(0,0,0,0);

    const int lane = tid & 31, w = tid >> 5;   // 16 warps

    for (int step = 0; step < nsteps; step++) {
        const int r = rtop - step;

        // stage tiles (idx<256 -> zt_s padded; else gbuf)
        if (tid < 256) {
            int fi = tid*4, i = fi >> 5, j = fi & 31;
            float* p = &zt_s[i*33 + j];
            p[0]=f0.x; p[1]=f0.y; p[2]=f0.z; p[3]=f0.w;
        } else {
            reinterpret_cast<float4*>(gbuf)[tid - 256] = f0;
        }
        if (ld2) reinterpret_cast<float4*>(gbuf)[tid + BNT - 256] = f1;
        if (step + 1 < nsteps) {
            f0 = ldtile(r-1, tid);
            if (ld2) f1 = ldtile(r-1, tid + BNT);
        }
        __syncthreads();

        float ztr[NX];
        #pragma unroll
        for (int j = 0; j < NX; j++) ztr[j] = zt_s[lane*33 + j];

        for (int m = w; m < 65; m += 16) {
            float a0 = gbuf[m*NX + lane], a1 = 0.f;
            #pragma unroll
            for (int j = 0; j < NX; j += 2) {
                a0 -= vw[m*33 + j]     * ztr[j];
                a1 += vw[m*33 + j + 1] * ztr[j+1];
            }
            vw[m*33 + lane] = a0 - a1;
        }
        __syncthreads();

        if (r <= rmainTop) {
            float* orow = out + (size_t)r * 2048;
            #pragma unroll
            for (int t = 0; t < 4; t++) {
                const int idx = tid + BNT*t;
                const int m = idx >> 5, i = idx & 31;
                orow[idx] = vw[i] + vw[(m+1)*33 + i];
            }
        }
    }
}

extern "C" void kernel_launch(void* const* d_in, const int* in_sizes, int n_in,
                              void* d_out, int out_size) {
    const float* hess  = (const float*)d_in[0];   // (8192,32,32)
    const float* grads = (const float*)d_in[1];   // (8192,1,32)
    const float* Amat  = (const float*)d_in[2];   // (32,32)
    const float* Ptp   = (const float*)d_in[3];   // (32,32)
    const float* Pinit = (const float*)d_in[4];   // (32,32)
    const float* epsx  = (const float*)d_in[5];   // (8192,64,32)
    float* out = (float*)d_out;                   // (8192,64,32)
    (void)in_sizes; (void)n_in; (void)out_size;

    fwd_kernel<<<FW_BLOCKS, 128>>>(hess, grads, Amat, Ptp, Pinit);
    prep_kernel<<<RR, PNT>>>(epsx);
    bwd_kernel<<<BW_BLOCKS, BNT>>>(out);
}

// round 13
// speedup vs baseline: 1.5991x; 1.1246x over previous
#include <cuda_runtime.h>
#include <cstdint>

#define RR 8192
#define NX 32
#define FW_S 8
#define FW_W 6
#define NCHAIN (RR/FW_S)         // 1024 chains, one warp each
#define FWPB 4                   // warps per block
#define FW_BLOCKS (NCHAIN/FWPB)  // 256
#define BW_S 16
#define BW_W 6
#define BW_BLOCKS (RR/BW_S)      // 512
#define BNT 512
#define PR_WPB 8
#define FULLM 0xffffffffu

// forward products
__device__ float g_Uh [RR*NX*NX];  // [r][j][k] = Uhat[k][j] (valid k<=j; junk below)
__device__ float g_off[RR*NX*NX];  // [r][j][k] = off[j][k]  (row-major off)
__device__ float g_rs [RR*NX];     // rstd diag
__device__ float g_u  [RR*NX];
// prep product
__device__ float g_LI [RR*NX*NX];  // [r][j][i] = Linv[i][j]  (column j per row)

// ---------------------------------------------------------------------------
// Forward: one WARP per chain (warm-up 6, chunk 8 -> 1024 chains). The 32x65
// augmented system [M | -ap | w] lives column-per-lane in registers; Gaussian
// elimination via warp shuffles — zero block barriers.
// ---------------------------------------------------------------------------
__global__ __launch_bounds__(128) void fwd_kernel(
    const float* __restrict__ hess, const float* __restrict__ grads,
    const float* __restrict__ Amat, const float* __restrict__ Ptp,
    const float* __restrict__ Pinit)
{
    __shared__ __align__(16) float C1[NX*33];     // Ptp + apat   (columns: [i*33+j])
    __shared__ __align__(16) float C0[NX*33];     // Ptp          (last step, mfac=0)
    __shared__ __align__(16) float Ci[NX*33];     // Pinit + apat (r==0)
    __shared__ __align__(16) float nap[NX*33];    // -ap
    __shared__ __align__(16) float offp[FWPB][NX*36+4];  // per-warp offT, stride 36

    const int tid = threadIdx.x, lane = tid & 31, w = tid >> 5;

    // ---- block init: ap = A@Ptp, apat = ap@A^T, build C0/C1/Ci/nap ----
    {
        float* A_s = offp[0];          // temp (stride 33)
        float* P_s = offp[2];          // temp
        for (int idx = tid; idx < NX*NX; idx += 128) {
            int i = idx >> 5, j = idx & 31;
            A_s[i*33+j] = Amat[idx];
            P_s[i*33+j] = Ptp[idx];
        }
        __syncthreads();
        for (int idx = tid; idx < NX*NX; idx += 128) {  // nap = -(A@P)
            int i = idx >> 5, j = idx & 31;
            float s = 0.f;
            #pragma unroll
            for (int k = 0; k < NX; k++) s += A_s[i*33+k]*P_s[k*33+j];
            nap[i*33+j] = -s;
        }
        __syncthreads();
        for (int idx = tid; idx < NX*NX; idx += 128) {  // apat = ap@A^T; C's
            int i = idx >> 5, j = idx & 31;
            float s = 0.f;
            #pragma unroll
            for (int k = 0; k < NX; k++) s -= nap[i*33+k]*A_s[j*33+k];
            const float P = P_s[i*33+j];
            C1[i*33+j] = P + s;
            C0[i*33+j] = P;
            Ci[i*33+j] = Pinit[idx] + s;
        }
        __syncthreads();
    }

    const int chain = blockIdx.x*FWPB + w;
    const int rmain = chain*FW_S;
    int r0 = rmain - FW_W; if (r0 < 0) r0 = 0;
    const int nsteps = rmain + FW_S - r0;
    float* op = offp[w];

    float a[NX], b[NX], rsd[NX], offr[NX], hp[NX];
    float gv, wv, uacc = 0.f;

    #pragma unroll
    for (int k = 0; k < NX; k++) { offr[k] = 0.f; op[k*36+lane] = 0.f; }
    __syncwarp();

    #pragma unroll
    for (int i = 0; i < NX; i++) hp[i] = hess[(size_t)r0*1024 + i*32 + lane];
    gv = grads[r0*NX + lane];

    for (int step = 0; step < nsteps; step++) {
        const int r = r0 + step;
        const float* Cp = (r == 0) ? Ci : ((r == RR-1) ? C0 : C1);

        // ---- build: a = C + hess - off^T off   (col of M), b = -ap col ----
        #pragma unroll
        for (int i = 0; i < NX; i++) a[i] = Cp[i*33+lane] + hp[i];
        #pragma unroll
        for (int k = 0; k < NX; k++) {
            const float ok = offr[k];
            #pragma unroll
            for (int i4 = 0; i4 < NX; i4 += 4) {
                const float4 v = *(const float4*)&op[k*36 + i4];
                a[i4]   -= v.x*ok; a[i4+1] -= v.y*ok;
                a[i4+2] -= v.z*ok; a[i4+3] -= v.w*ok;
            }
        }
        #pragma unroll
        for (int i = 0; i < NX; i++) b[i] = nap[i*33+lane];
        wv = gv - uacc;   // w[lane] = grad[lane] - u . off[lane][:]

        if (step + 1 < nsteps) {   // prefetch next hess/grad under elimination
            #pragma unroll
            for (int i = 0; i < NX; i++) hp[i] = hess[(size_t)(r+1)*1024 + i*32 + lane];
            gv = grads[(r+1)*NX + lane];
        }

        // ---- shuffle elimination (no barriers, no per-update multiply) ----
        float dmine = 1.f;
        #pragma unroll
        for (int k = 0; k < NX; k++) {
            const float dk = __shfl_sync(FULLM, a[k], k);
            rsd[k] = dk;
            dmine = (lane == k) ? dk : dmine;
            const float invd = __frcp_rn(dk);
            const float ak_s = a[k]*invd;   // lane-local scaled pivot row entries
            const float bk_s = b[k]*invd;
            #pragma unroll
            for (int i = k+1; i < NX; i++) {
                const float t = __shfl_sync(FULLM, a[i], k);
                a[i] -= t*ak_s;
                b[i] -= t*bk_s;
            }
        }
        #pragma unroll
        for (int k = 0; k < NX; k++) rsd[k] = __frsqrt_rn(rsd[k]);
        const float rsmine = __frsqrt_rn(dmine);

        // ---- eliminate w: t_ik = Uhat[k][i]*invd_k = a[k]*rs_k^2 (local) ----
        #pragma unroll
        for (int k = 0; k < NX; k++) {
            const float wk = __shfl_sync(FULLM, wv, k);
            const float t = (lane > k) ? a[k]*rsd[k]*rsd[k] : 0.f;
            wv -= t*wk;
        }

        // ---- extraction: off row, u-dot for next w, smem offT ----
        uacc = 0.f;
        #pragma unroll
        for (int k = 0; k < NX; k++) {
            offr[k] = b[k]*rsd[k];
            const float uk = __shfl_sync(FULLM, wv, k) * rsd[k];
            uacc += uk*offr[k];
            op[k*36+lane] = offr[k];
        }
        __syncwarp();

        if (r >= rmain) {
            const size_t rb = (size_t)r*(NX*NX) + lane*NX;
            #pragma unroll
            for (int k4 = 0; k4 < NX; k4 += 4) {
                *(float4*)&g_off[rb+k4] = make_float4(offr[k4],offr[k4+1],offr[k4+2],offr[k4+3]);
                *(float4*)&g_Uh [rb+k4] = make_float4(a[k4],a[k4+1],a[k4+2],a[k4+3]);
            }
            g_rs[r*NX+lane] = rsmine;
            g_u [r*NX+lane] = wv * rsmine;
        }
    }
}

// ---------------------------------------------------------------------------
// prep: ONE WARP PER r — invert L entirely in registers via shuffles.
// Lane j computes Linv column j: x[i] = Linv[i][j].
//   L[i][k] = Uhat[k][i]*rs_k (k<i), L[i][i] = 1/rs_i, Linv[i][i] = rs_i.
//   x[i] = -rs_i * sum_{k<i} L[i][k]*x[k]   (L[i][k] broadcast from lane i)
// Stores g_LI[r][j][i] = Linv[i][j].
// ---------------------------------------------------------------------------
__global__ __launch_bounds__(256) void prep_kernel()
{
    const int lane = threadIdx.x & 31, w = threadIdx.x >> 5;
    const int r = blockIdx.x*PR_WPB + w;
    const size_t rb = (size_t)r*1024 + lane*32;

    float uc[32];
    #pragma unroll
    for (int k4 = 0; k4 < 32; k4 += 4) {
        float4 v = *(const float4*)&g_Uh[rb + k4];
        uc[k4]=v.x; uc[k4+1]=v.y; uc[k4+2]=v.z; uc[k4+3]=v.w;
    }
    const float rsv = g_rs[r*32 + lane];
    float rsk[32];
    #pragma unroll
    for (int k = 0; k < 32; k++) rsk[k] = __shfl_sync(FULLM, rsv, k);
    // lrow on lane i: uc[k]*rsk[k] = L[i][k] (valid k<i)
    #pragma unroll
    for (int k = 0; k < 32; k++) uc[k] *= rsk[k];

    float x[32];
    #pragma unroll
    for (int i = 0; i < 32; i++) x[i] = (i == lane) ? rsv : 0.f;
    #pragma unroll
    for (int i = 1; i < 32; i++) {
        float s = 0.f;
        #pragma unroll
        for (int k = 0; k < i; k++) {
            const float Lik = __shfl_sync(FULLM, uc[k], i);
            s += Lik * x[k];
        }
        if (lane < i) x[i] = -rsk[i]*s;
    }
    #pragma unroll
    for (int i4 = 0; i4 < 32; i4 += 4)
        *(float4*)&g_LI[rb + i4] = make_float4(x[i4],x[i4+1],x[i4+2],x[i4+3]);
}

// ---------------------------------------------------------------------------
// Backward: chunked reverse scan (warm-up 6, chunk 16 -> 512 blocks, single
// wave). Per step: vw' = (g - vw @ off) @ Linv, two warp-private matmul
// phases (row m owned by one warp in both) — only __syncwarp between them.
// g rows read straight from epsx/g_u (no G precompute, no ZT).
// ---------------------------------------------------------------------------
__global__ __launch_bounds__(BNT) void bwd_kernel(
    const float* __restrict__ epsx, float* __restrict__ out)
{
    __shared__ float vw  [65*33];
    __shared__ float tmp [65*33];
    __shared__ float off_s[NX*33];   // off_s[i*33+j] = off[i][j]
    __shared__ float li_s [NX*33];   // li_s[j*33+i]  = Linv[i][j]
    __shared__ float u_s[NX];

    const int tid = threadIdx.x;
    const int b   = blockIdx.x;
    const int lane = tid & 31, w = tid >> 5;   // 16 warps
    const int rlow     = b*BW_S;
    const int rmainTop = rlow + BW_S - 1;
    int rtop = rmainTop + BW_W; if (rtop > RR-1) rtop = RR-1;
    const int nsteps = rtop - rlow + 1;

    for (int idx = tid; idx < 65*33; idx += BNT) vw[idx] = 0.f;

    float4 pf; float uval = 0.f; float gval[5];
    // prefetch tiles + g rows for r
    auto prefetch = [&](int r) {
        const size_t rb = (size_t)r*1024;
        if (tid < 256) pf = ((const float4*)(g_off + rb))[tid];
        else           pf = ((const float4*)(g_LI  + rb))[tid - 256];
        if (tid < NX) uval = g_u[r*NX + tid];
        #pragma unroll
        for (int t = 0; t < 5; t++) {
            const int m = w + 16*t;
            if (m >= 1 && m < 65) gval[t] = epsx[(size_t)r*2048 + (m-1)*32 + lane];
        }
    };
    prefetch(rtop);

    for (int step = 0; step < nsteps; step++) {
        const int r = rtop - step;

        __syncthreads();   // B1: prior step's vw reads (store) complete
        // ---- stage tiles ----
        {
            const int fi = (tid & 255)*4, i = fi >> 5, j = fi & 31;
            float* dst = (tid < 256) ? &off_s[i*33 + j] : &li_s[i*33 + j];
            dst[0]=pf.x; dst[1]=pf.y; dst[2]=pf.z; dst[3]=pf.w;
            if (tid < NX) u_s[tid] = uval;
        }
        float gcur[5];
        #pragma unroll
        for (int t = 0; t < 5; t++) gcur[t] = gval[t];
        if (step + 1 < nsteps) prefetch(r-1);
        __syncthreads();   // B2: off_s/li_s/u_s visible

        // lane-cached columns
        float ofr[NX], ltr[NX];
        #pragma unroll
        for (int i = 0; i < NX; i++) ofr[i] = off_s[i*33 + lane];   // off[i][lane]
        #pragma unroll
        for (int k = 0; k < NX; k++) ltr[k] = li_s[lane*33 + k];    // Linv[k][lane]

        // phase 1: tmp[m][lane] = g[m][lane] - sum_i vw[m][i]*off[i][lane]
        #pragma unroll
        for (int t = 0; t < 5; t++) {
            const int m = w + 16*t;
            if (m < 65) {
                float s = (m == 0) ? u_s[lane] : gcur[t];
                #pragma unroll
                for (int i = 0; i < NX; i++) s -= vw[m*33 + i]*ofr[i];
                tmp[m*33 + lane] = s;
            }
        }
        __syncwarp();
        // phase 2: vw[m][lane] = sum_k tmp[m][k]*Linv[k][lane]
        #pragma unroll
        for (int t = 0; t < 5; t++) {
            const int m = w + 16*t;
            if (m < 65) {
                float s = 0.f;
                #pragma unroll
                for (int k = 0; k < NX; k++) s += tmp[m*33 + k]*ltr[k];
                vw[m*33 + lane] = s;
            }
        }
        __syncthreads();   // B3: vw complete before cross-warp output read

        if (r <= rmainTop) {
            float* orow = out + (size_t)r * 2048;
            #pragma unroll
            for (int t = 0; t < 4; t++) {
                const int idx = tid + BNT*t;
                const int m = idx >> 5, i = idx & 31;
                orow[idx] = vw[i] + vw[(m+1)*33 + i];
            }
        }
    }
}

extern "C" void kernel_launch(void* const* d_in, const int* in_sizes, int n_in,
                              void* d_out, int out_size) {
    const float* hess  = (const float*)d_in[0];   // (8192,32,32)
    const float* grads = (const float*)d_in[1];   // (8192,1,32)
    const float* Amat  = (const float*)d_in[2];   // (32,32)
    const float* Ptp   = (const float*)d_in[3];   // (32,32)
    const float* Pinit = (const float*)d_in[4];   // (32,32)
    const float* epsx  = (const float*)d_in[5];   // (8192,64,32)
    float* out = (float*)d_out;                   // (8192,64,32)
    (void)in_sizes; (void)n_in; (void)out_size;

    fwd_kernel<<<FW_BLOCKS, 128>>>(hess, grads, Amat, Ptp, Pinit);
    prep_kernel<<<RR/PR_WPB, 256>>>();
    bwd_kernel<<<BW_BLOCKS, BNT>>>(epsx, out);
}

// round 14
// speedup vs baseline: 2.1639x; 1.3532x over previous
#include <cuda_runtime.h>
#include <cstdint>

#define RR 8192
#define NX 32
#define FW_S 8
#define FW_W 5
#define NCHAIN (RR/FW_S)         // 1024 chains, one warp each
#define FWPB 4                   // warps per block
#define FW_BLOCKS (NCHAIN/FWPB)  // 256
#define BW_S 16
#define BW_W 5
#define BW_BLOCKS (RR/BW_S)      // 512
#define BNT 512
#define PR_WPB 8
#define VST 36                   // vw/tmp row stride (16B aligned)
#define FULLM 0xffffffffu

// forward products
__device__ float g_Uh [RR*NX*NX];  // [r][j][k] = Uhat[k][j] (valid k<=j; junk below)
__device__ float g_off[RR*NX*NX];  // [r][j][k] = off[j][k]  (row-major off)
__device__ float g_rs [RR*NX];     // rstd diag
__device__ float g_u  [RR*NX];
// prep product
__device__ float g_LI [RR*NX*NX];  // [r][j][i] = Linv[i][j]  (column j per row)

// ---------------------------------------------------------------------------
// Forward: one WARP per chain (warm-up 5, chunk 8 -> 1024 chains). The 32x65
// augmented system [M | -ap | w] lives column-per-lane in registers; Gaussian
// elimination via warp shuffles — zero block barriers.
// ---------------------------------------------------------------------------
__global__ __launch_bounds__(128) void fwd_kernel(
    const float* __restrict__ hess, const float* __restrict__ grads,
    const float* __restrict__ Amat, const float* __restrict__ Ptp,
    const float* __restrict__ Pinit)
{
    __shared__ __align__(16) float C1[NX*33];     // Ptp + apat   (columns: [i*33+j])
    __shared__ __align__(16) float C0[NX*33];     // Ptp          (last step, mfac=0)
    __shared__ __align__(16) float Ci[NX*33];     // Pinit + apat (r==0)
    __shared__ __align__(16) float nap[NX*33];    // -ap
    __shared__ __align__(16) float offp[FWPB][NX*36+4];  // per-warp offT, stride 36

    const int tid = threadIdx.x, lane = tid & 31, w = tid >> 5;

    // ---- block init: ap = A@Ptp, apat = ap@A^T, build C0/C1/Ci/nap ----
    {
        float* A_s = offp[0];          // temp (stride 33)
        float* P_s = offp[2];          // temp
        for (int idx = tid; idx < NX*NX; idx += 128) {
            int i = idx >> 5, j = idx & 31;
            A_s[i*33+j] = Amat[idx];
            P_s[i*33+j] = Ptp[idx];
        }
        __syncthreads();
        for (int idx = tid; idx < NX*NX; idx += 128) {  // nap = -(A@P)
            int i = idx >> 5, j = idx & 31;
            float s = 0.f;
            #pragma unroll
            for (int k = 0; k < NX; k++) s += A_s[i*33+k]*P_s[k*33+j];
            nap[i*33+j] = -s;
        }
        __syncthreads();
        for (int idx = tid; idx < NX*NX; idx += 128) {  // apat = ap@A^T; C's
            int i = idx >> 5, j = idx & 31;
            float s = 0.f;
            #pragma unroll
            for (int k = 0; k < NX; k++) s -= nap[i*33+k]*A_s[j*33+k];
            const float P = P_s[i*33+j];
            C1[i*33+j] = P + s;
            C0[i*33+j] = P;
            Ci[i*33+j] = Pinit[idx] + s;
        }
        __syncthreads();
    }

    const int chain = blockIdx.x*FWPB + w;
    const int rmain = chain*FW_S;
    int r0 = rmain - FW_W; if (r0 < 0) r0 = 0;
    const int nsteps = rmain + FW_S - r0;
    float* op = offp[w];

    float a[NX], b[NX], rsd[NX], offr[NX], hp[NX];
    float gv, wv, uacc = 0.f;

    #pragma unroll
    for (int k = 0; k < NX; k++) { offr[k] = 0.f; op[k*36+lane] = 0.f; }
    __syncwarp();

    #pragma unroll
    for (int i = 0; i < NX; i++) hp[i] = hess[(size_t)r0*1024 + i*32 + lane];
    gv = grads[r0*NX + lane];

    for (int step = 0; step < nsteps; step++) {
        const int r = r0 + step;
        const float* Cp = (r == 0) ? Ci : ((r == RR-1) ? C0 : C1);

        // ---- build: a = C + hess - off^T off   (col of M), b = -ap col ----
        #pragma unroll
        for (int i = 0; i < NX; i++) a[i] = Cp[i*33+lane] + hp[i];
        #pragma unroll
        for (int k = 0; k < NX; k++) {
            const float ok = offr[k];
            #pragma unroll
            for (int i4 = 0; i4 < NX; i4 += 4) {
                const float4 v = *(const float4*)&op[k*36 + i4];
                a[i4]   -= v.x*ok; a[i4+1] -= v.y*ok;
                a[i4+2] -= v.z*ok; a[i4+3] -= v.w*ok;
            }
        }
        #pragma unroll
        for (int i = 0; i < NX; i++) b[i] = nap[i*33+lane];
        wv = gv - uacc;   // w[lane] = grad[lane] - u . off[lane][:]

        if (step + 1 < nsteps) {   // prefetch next hess/grad under elimination
            #pragma unroll
            for (int i = 0; i < NX; i++) hp[i] = hess[(size_t)(r+1)*1024 + i*32 + lane];
            gv = grads[(r+1)*NX + lane];
        }

        // ---- shuffle elimination (no barriers, no per-update multiply) ----
        float dmine = 1.f;
        #pragma unroll
        for (int k = 0; k < NX; k++) {
            const float dk = __shfl_sync(FULLM, a[k], k);
            rsd[k] = dk;
            dmine = (lane == k) ? dk : dmine;
            const float invd = __frcp_rn(dk);
            const float ak_s = a[k]*invd;   // lane-local scaled pivot row entries
            const float bk_s = b[k]*invd;
            #pragma unroll
            for (int i = k+1; i < NX; i++) {
                const float t = __shfl_sync(FULLM, a[i], k);
                a[i] -= t*ak_s;
                b[i] -= t*bk_s;
            }
        }
        #pragma unroll
        for (int k = 0; k < NX; k++) rsd[k] = __frsqrt_rn(rsd[k]);
        const float rsmine = __frsqrt_rn(dmine);

        // ---- eliminate w: t_ik = Uhat[k][i]*invd_k = a[k]*rs_k^2 (local) ----
        #pragma unroll
        for (int k = 0; k < NX; k++) {
            const float wk = __shfl_sync(FULLM, wv, k);
            const float t = (lane > k) ? a[k]*rsd[k]*rsd[k] : 0.f;
            wv -= t*wk;
        }

        // ---- extraction: off row, u-dot for next w, smem offT ----
        uacc = 0.f;
        #pragma unroll
        for (int k = 0; k < NX; k++) {
            offr[k] = b[k]*rsd[k];
            const float uk = __shfl_sync(FULLM, wv, k) * rsd[k];
            uacc += uk*offr[k];
            op[k*36+lane] = offr[k];
        }
        __syncwarp();

        if (r >= rmain) {
            const size_t rb = (size_t)r*(NX*NX) + lane*NX;
            #pragma unroll
            for (int k4 = 0; k4 < NX; k4 += 4) {
                *(float4*)&g_off[rb+k4] = make_float4(offr[k4],offr[k4+1],offr[k4+2],offr[k4+3]);
                *(float4*)&g_Uh [rb+k4] = make_float4(a[k4],a[k4+1],a[k4+2],a[k4+3]);
            }
            g_rs[r*NX+lane] = rsmine;
            g_u [r*NX+lane] = wv * rsmine;
        }
    }
}

// ---------------------------------------------------------------------------
// prep: ONE WARP PER r — invert L entirely in registers via shuffles.
// Lane j computes Linv column j; stores g_LI[r][j][i] = Linv[i][j].
// ---------------------------------------------------------------------------
__global__ __launch_bounds__(256) void prep_kernel()
{
    const int lane = threadIdx.x & 31, w = threadIdx.x >> 5;
    const int r = blockIdx.x*PR_WPB + w;
    const size_t rb = (size_t)r*1024 + lane*32;

    float uc[32];
    #pragma unroll
    for (int k4 = 0; k4 < 32; k4 += 4) {
        float4 v = *(const float4*)&g_Uh[rb + k4];
        uc[k4]=v.x; uc[k4+1]=v.y; uc[k4+2]=v.z; uc[k4+3]=v.w;
    }
    const float rsv = g_rs[r*32 + lane];
    float rsk[32];
    #pragma unroll
    for (int k = 0; k < 32; k++) rsk[k] = __shfl_sync(FULLM, rsv, k);
    #pragma unroll
    for (int k = 0; k < 32; k++) uc[k] *= rsk[k];   // lane i: uc[k] = L[i][k] (k<i)

    float x[32];
    #pragma unroll
    for (int i = 0; i < 32; i++) x[i] = (i == lane) ? rsv : 0.f;
    #pragma unroll
    for (int i = 1; i < 32; i++) {
        float s = 0.f;
        #pragma unroll
        for (int k = 0; k < i; k++) {
            const float Lik = __shfl_sync(FULLM, uc[k], i);
            s += Lik * x[k];
        }
        if (lane < i) x[i] = -rsk[i]*s;
    }
    #pragma unroll
    for (int i4 = 0; i4 < 32; i4 += 4)
        *(float4*)&g_LI[rb + i4] = make_float4(x[i4],x[i4+1],x[i4+2],x[i4+3]);
}

// ---------------------------------------------------------------------------
// Backward: chunked reverse scan (warm-up 5, chunk 16 -> 512 blocks, single
// wave). Per step: vw' = (g - vw @ off) @ Linv, two warp-private matmul
// phases with float4 broadcast loads (vw/tmp stride 36); 2 block barriers.
// ---------------------------------------------------------------------------
__global__ __launch_bounds__(BNT) void bwd_kernel(
    const float* __restrict__ epsx, float* __restrict__ out)
{
    __shared__ __align__(16) float vw  [65*VST];
    __shared__ __align__(16) float tmp [65*VST];
    __shared__ float off_s[NX*33];   // off_s[i*33+j] = off[i][j]
    __shared__ __align__(16) float li_s [NX*VST];  // li_s[j*36+k] = Linv[k][j]
    __shared__ float u_s[NX];

    const int tid = threadIdx.x;
    const int b   = blockIdx.x;
    const int lane = tid & 31, w = tid >> 5;   // 16 warps
    const int rlow     = b*BW_S;
    const int rmainTop = rlow + BW_S - 1;
    int rtop = rmainTop + BW_W; if (rtop > RR-1) rtop = RR-1;
    const int nsteps = rtop - rlow + 1;

    for (int idx = tid; idx < 65*VST; idx += BNT) vw[idx] = 0.f;

    float4 pf; float uval = 0.f; float gval[5];
    auto prefetch = [&](int r) {
        const size_t rb = (size_t)r*1024;
        if (tid < 256) pf = ((const float4*)(g_off + rb))[tid];
        else           pf = ((const float4*)(g_LI  + rb))[tid - 256];
        if (tid < NX) uval = g_u[r*NX + tid];
        #pragma unroll
        for (int t = 0; t < 5; t++) {
            const int m = w + 16*t;
            if (m >= 1 && m < 65) gval[t] = epsx[(size_t)r*2048 + (m-1)*32 + lane];
        }
    };
    prefetch(rtop);

    for (int step = 0; step < nsteps; step++) {
        const int r = rtop - step;

        // ---- stage tiles (off_s stride 33; li_s stride 36) ----
        {
            const int fi = (tid & 255)*4, i = fi >> 5, j = fi & 31;
            if (tid < 256) {
                float* dst = &off_s[i*33 + j];
                dst[0]=pf.x; dst[1]=pf.y; dst[2]=pf.z; dst[3]=pf.w;
            } else {
                *(float4*)&li_s[i*VST + j] = pf;
            }
            if (tid < NX) u_s[tid] = uval;
        }
        float gcur[5];
        #pragma unroll
        for (int t = 0; t < 5; t++) gcur[t] = gval[t];
        if (step + 1 < nsteps) prefetch(r-1);
        __syncthreads();   // B2: staging visible; also orders prior output reads

        // lane-cached columns
        float ofr[NX], ltr[NX];
        #pragma unroll
        for (int i = 0; i < NX; i++) ofr[i] = off_s[i*33 + lane];   // off[i][lane]
        #pragma unroll
        for (int k4 = 0; k4 < NX; k4 += 4) {
            const float4 v = *(const float4*)&li_s[lane*VST + k4];  // Linv[k][lane]
            ltr[k4]=v.x; ltr[k4+1]=v.y; ltr[k4+2]=v.z; ltr[k4+3]=v.w;
        }

        // phase 1: tmp[m][lane] = g[m][lane] - sum_i vw[m][i]*off[i][lane]
        #pragma unroll
        for (int t = 0; t < 5; t++) {
            const int m = w + 16*t;
            if (m < 65) {
                float s = (m == 0) ? u_s[lane] : gcur[t];
                const float4* vp = (const float4*)&vw[m*VST];
                #pragma unroll
                for (int q = 0; q < 8; q++) {
                    const float4 v4 = vp[q];
                    s -= v4.x*ofr[4*q] + v4.y*ofr[4*q+1] + v4.z*ofr[4*q+2] + v4.w*ofr[4*q+3];
                }
                tmp[m*VST + lane] = s;
            }
        }
        __syncwarp();
        // phase 2: vw[m][lane] = sum_k tmp[m][k]*Linv[k][lane]
        #pragma unroll
        for (int t = 0; t < 5; t++) {
            const int m = w + 16*t;
            if (m < 65) {
                float s = 0.f;
                const float4* tp = (const float4*)&tmp[m*VST];
                #pragma unroll
                for (int q = 0; q < 8; q++) {
                    const float4 t4 = tp[q];
                    s += t4.x*ltr[4*q] + t4.y*ltr[4*q+1] + t4.z*ltr[4*q+2] + t4.w*ltr[4*q+3];
                }
                vw[m*VST + lane] = s;
            }
        }
        __syncthreads();   // B3: vw complete before cross-warp output read

        if (r <= rmainTop) {
            float* orow = out + (size_t)r * 2048;
            #pragma unroll
            for (int t = 0; t < 4; t++) {
                const int idx = tid + BNT*t;
                const int m = idx >> 5, i = idx & 31;
                orow[idx] = vw[i] + vw[(m+1)*VST + i];
            }
        }
    }
}

extern "C" void kernel_launch(void* const* d_in, const int* in_sizes, int n_in,
                              void* d_out, int out_size) {
    const float* hess  = (const float*)d_in[0];   // (8192,32,32)
    const float* grads = (const float*)d_in[1];   // (8192,1,32)
    const float* Amat  = (const float*)d_in[2];   // (32,32)
    const float* Ptp   = (const float*)d_in[3];   // (32,32)
    const float* Pinit = (const float*)d_in[4];   // (32,32)
    const float* epsx  = (const float*)d_in[5];   // (8192,64,32)
    float* out = (float*)d_out;                   // (8192,64,32)
    (void)in_sizes; (void)n_in; (void)out_size;

    fwd_kernel<<<FW_BLOCKS, 128>>>(hess, grads, Amat, Ptp, Pinit);
    prep_kernel<<<RR/PR_WPB, 256>>>();
    bwd_kernel<<<BW_BLOCKS, BNT>>>(epsx, out);
}

// round 15
// speedup vs baseline: 2.6467x; 1.2231x over previous
#include <cuda_runtime.h>
#include <cstdint>

#define RR 8192
#define NX 32
#define FW_S 8
#define FW_W 4
#define NCHAIN (RR/FW_S)         // 1024 chains, one warp each
#define FWPB 4                   // warps per block
#define FW_BLOCKS (NCHAIN/FWPB)  // 256
#define BW_S 32
#define BW_W 6
#define BW_BLOCKS (RR/BW_S)      // 256
#define BNT 256
#define PR_WPB 8
#define VST 36                   // vw/tmp/offT/li row stride (16B aligned)
#define FULLM 0xffffffffu

// forward products
__device__ float g_Uh [RR*NX*NX];  // [r][j][k] = Uhat[k][j] (valid k<=j; junk below)
__device__ float g_off[RR*NX*NX];  // [r][j][k] = off[j][k]  (row-major off)
__device__ float g_rs [RR*NX];     // rstd diag
__device__ float g_u  [RR*NX];
// prep product
__device__ float g_LI [RR*NX*NX];  // [r][j][i] = Linv[i][j]  (column j per row)

// ---------------------------------------------------------------------------
// Forward: one WARP per chain (warm-up 4, chunk 8 -> 1024 chains). The 32x65
// augmented system [M | -ap | w] lives column-per-lane in registers; Gaussian
// elimination via warp shuffles — zero block barriers.
// ---------------------------------------------------------------------------
__global__ __launch_bounds__(128) void fwd_kernel(
    const float* __restrict__ hess, const float* __restrict__ grads,
    const float* __restrict__ Amat, const float* __restrict__ Ptp,
    const float* __restrict__ Pinit)
{
    __shared__ __align__(16) float C1[NX*33];     // Ptp + apat   (columns: [i*33+j])
    __shared__ __align__(16) float C0[NX*33];     // Ptp          (last step, mfac=0)
    __shared__ __align__(16) float Ci[NX*33];     // Pinit + apat (r==0)
    __shared__ __align__(16) float nap[NX*33];    // -ap
    __shared__ __align__(16) float offp[FWPB][NX*36+4];  // per-warp offT, stride 36

    const int tid = threadIdx.x, lane = tid & 31, w = tid >> 5;

    // ---- block init: ap = A@Ptp, apat = ap@A^T, build C0/C1/Ci/nap ----
    {
        float* A_s = offp[0];          // temp (stride 33)
        float* P_s = offp[2];          // temp
        for (int idx = tid; idx < NX*NX; idx += 128) {
            int i = idx >> 5, j = idx & 31;
            A_s[i*33+j] = Amat[idx];
            P_s[i*33+j] = Ptp[idx];
        }
        __syncthreads();
        for (int idx = tid; idx < NX*NX; idx += 128) {  // nap = -(A@P)
            int i = idx >> 5, j = idx & 31;
            float s = 0.f;
            #pragma unroll
            for (int k = 0; k < NX; k++) s += A_s[i*33+k]*P_s[k*33+j];
            nap[i*33+j] = -s;
        }
        __syncthreads();
        for (int idx = tid; idx < NX*NX; idx += 128) {  // apat = ap@A^T; C's
            int i = idx >> 5, j = idx & 31;
            float s = 0.f;
            #pragma unroll
            for (int k = 0; k < NX; k++) s -= nap[i*33+k]*A_s[j*33+k];
            const float P = P_s[i*33+j];
            C1[i*33+j] = P + s;
            C0[i*33+j] = P;
            Ci[i*33+j] = Pinit[idx] + s;
        }
        __syncthreads();
    }

    const int chain = blockIdx.x*FWPB + w;
    const int rmain = chain*FW_S;
    int r0 = rmain - FW_W; if (r0 < 0) r0 = 0;
    const int nsteps = rmain + FW_S - r0;
    float* op = offp[w];

    float a[NX], b[NX], rsd[NX], offr[NX], hp[NX];
    float gv, wv, uacc = 0.f;

    #pragma unroll
    for (int k = 0; k < NX; k++) { offr[k] = 0.f; op[k*36+lane] = 0.f; }
    __syncwarp();

    #pragma unroll
    for (int i = 0; i < NX; i++) hp[i] = hess[(size_t)r0*1024 + i*32 + lane];
    gv = grads[r0*NX + lane];

    for (int step = 0; step < nsteps; step++) {
        const int r = r0 + step;
        const float* Cp = (r == 0) ? Ci : ((r == RR-1) ? C0 : C1);

        // ---- build: a = C + hess - off^T off   (col of M), b = -ap col ----
        #pragma unroll
        for (int i = 0; i < NX; i++) a[i] = Cp[i*33+lane] + hp[i];
        #pragma unroll
        for (int k = 0; k < NX; k++) {
            const float ok = offr[k];
            #pragma unroll
            for (int i4 = 0; i4 < NX; i4 += 4) {
                const float4 v = *(const float4*)&op[k*36 + i4];
                a[i4]   -= v.x*ok; a[i4+1] -= v.y*ok;
                a[i4+2] -= v.z*ok; a[i4+3] -= v.w*ok;
            }
        }
        #pragma unroll
        for (int i = 0; i < NX; i++) b[i] = nap[i*33+lane];
        wv = gv - uacc;   // w[lane] = grad[lane] - u . off[lane][:]

        if (step + 1 < nsteps) {   // prefetch next hess/grad under elimination
            #pragma unroll
            for (int i = 0; i < NX; i++) hp[i] = hess[(size_t)(r+1)*1024 + i*32 + lane];
            gv = grads[(r+1)*NX + lane];
        }

        // ---- shuffle elimination (no barriers, no per-update multiply) ----
        float dmine = 1.f;
        #pragma unroll
        for (int k = 0; k < NX; k++) {
            const float dk = __shfl_sync(FULLM, a[k], k);
            rsd[k] = dk;
            dmine = (lane == k) ? dk : dmine;
            const float invd = __frcp_rn(dk);
            const float ak_s = a[k]*invd;   // lane-local scaled pivot row entries
            const float bk_s = b[k]*invd;
            #pragma unroll
            for (int i = k+1; i < NX; i++) {
                const float t = __shfl_sync(FULLM, a[i], k);
                a[i] -= t*ak_s;
                b[i] -= t*bk_s;
            }
        }
        #pragma unroll
        for (int k = 0; k < NX; k++) rsd[k] = __frsqrt_rn(rsd[k]);
        const float rsmine = __frsqrt_rn(dmine);

        // ---- eliminate w: t_ik = Uhat[k][i]*invd_k = a[k]*rs_k^2 (local) ----
        #pragma unroll
        for (int k = 0; k < NX; k++) {
            const float wk = __shfl_sync(FULLM, wv, k);
            const float t = (lane > k) ? a[k]*rsd[k]*rsd[k] : 0.f;
            wv -= t*wk;
        }

        // ---- extraction: off row, u-dot for next w, smem offT ----
        uacc = 0.f;
        #pragma unroll
        for (int k = 0; k < NX; k++) {
            offr[k] = b[k]*rsd[k];
            const float uk = __shfl_sync(FULLM, wv, k) * rsd[k];
            uacc += uk*offr[k];
            op[k*36+lane] = offr[k];
        }
        __syncwarp();

        if (r >= rmain) {
            const size_t rb = (size_t)r*(NX*NX) + lane*NX;
            #pragma unroll
            for (int k4 = 0; k4 < NX; k4 += 4) {
                *(float4*)&g_off[rb+k4] = make_float4(offr[k4],offr[k4+1],offr[k4+2],offr[k4+3]);
                *(float4*)&g_Uh [rb+k4] = make_float4(a[k4],a[k4+1],a[k4+2],a[k4+3]);
            }
            g_rs[r*NX+lane] = rsmine;
            g_u [r*NX+lane] = wv * rsmine;
        }
    }
}

// ---------------------------------------------------------------------------
// prep: ONE WARP PER r — invert L entirely in registers via shuffles.
// Lane j computes Linv column j; stores g_LI[r][j][i] = Linv[i][j].
// ---------------------------------------------------------------------------
__global__ __launch_bounds__(256) void prep_kernel()
{
    const int lane = threadIdx.x & 31, w = threadIdx.x >> 5;
    const int r = blockIdx.x*PR_WPB + w;
    const size_t rb = (size_t)r*1024 + lane*32;

    float uc[32];
    #pragma unroll
    for (int k4 = 0; k4 < 32; k4 += 4) {
        float4 v = *(const float4*)&g_Uh[rb + k4];
        uc[k4]=v.x; uc[k4+1]=v.y; uc[k4+2]=v.z; uc[k4+3]=v.w;
    }
    const float rsv = g_rs[r*32 + lane];
    float rsk[32];
    #pragma unroll
    for (int k = 0; k < 32; k++) rsk[k] = __shfl_sync(FULLM, rsv, k);
    #pragma unroll
    for (int k = 0; k < 32; k++) uc[k] *= rsk[k];   // lane i: uc[k] = L[i][k] (k<i)

    float x[32];
    #pragma unroll
    for (int i = 0; i < 32; i++) x[i] = (i == lane) ? rsv : 0.f;
    #pragma unroll
    for (int i = 1; i < 32; i++) {
        float s = 0.f;
        #pragma unroll
        for (int k = 0; k < i; k++) {
            const float Lik = __shfl_sync(FULLM, uc[k], i);
            s += Lik * x[k];
        }
        if (lane < i) x[i] = -rsk[i]*s;
    }
    #pragma unroll
    for (int i4 = 0; i4 < 32; i4 += 4)
        *(float4*)&g_LI[rb + i4] = make_float4(x[i4],x[i4+1],x[i4+2],x[i4+3]);
}

// ---------------------------------------------------------------------------
// Backward: chunked reverse scan (warm-up 6, chunk 32 -> 256 blocks of 256
// threads, 2 blocks/SM = single wave). Per step: vw' = (g - vw@off) @ Linv,
// two warp-private matmul phases, float4 broadcast loads throughout.
// ---------------------------------------------------------------------------
__global__ __launch_bounds__(BNT, 2) void bwd_kernel(
    const float* __restrict__ epsx, float* __restrict__ out)
{
    __shared__ __align__(16) float vw  [65*VST];
    __shared__ __align__(16) float tmp [65*VST];
    __shared__ __align__(16) float offT_s[NX*VST];  // [j*36+i] = off[i][j]
    __shared__ __align__(16) float li_s  [NX*VST];  // [j*36+k] = Linv[k][j]
    __shared__ float u_s[NX];

    const int tid = threadIdx.x;
    const int b   = blockIdx.x;
    const int lane = tid & 31, w = tid >> 5;   // 8 warps
    const int rlow     = b*BW_S;
    const int rmainTop = rlow + BW_S - 1;
    int rtop = rmainTop + BW_W; if (rtop > RR-1) rtop = RR-1;
    const int nsteps = rtop - rlow + 1;

    for (int idx = tid; idx < 65*VST; idx += BNT) vw[idx] = 0.f;

    float4 pf0, pf1; float uval = 0.f; float gval[9];
    auto prefetch = [&](int r) {
        const size_t rb = (size_t)r*1024;
        pf0 = ((const float4*)(g_off + rb))[tid];
        pf1 = ((const float4*)(g_LI  + rb))[tid];
        if (tid < NX) uval = g_u[r*NX + tid];
        #pragma unroll
        for (int t = 0; t < 9; t++) {
            const int m = w + 8*t;
            if (m >= 1 && m < 65) gval[t] = epsx[(size_t)r*2048 + (m-1)*32 + lane];
        }
    };
    prefetch(rtop);

    for (int step = 0; step < nsteps; step++) {
        const int r = rtop - step;

        // ---- stage tiles: off transposed (scatter), Linv rows (float4) ----
        {
            const int fi = tid*4, j = fi >> 5, k = fi & 31;
            offT_s[(k+0)*VST + j] = pf0.x;
            offT_s[(k+1)*VST + j] = pf0.y;
            offT_s[(k+2)*VST + j] = pf0.z;
            offT_s[(k+3)*VST + j] = pf0.w;
            *(float4*)&li_s[j*VST + k] = pf1;
            if (tid < NX) u_s[tid] = uval;
        }
        float gcur[9];
        #pragma unroll
        for (int t = 0; t < 9; t++) gcur[t] = gval[t];
        if (step + 1 < nsteps) prefetch(r-1);
        __syncthreads();   // B2: staging visible; orders prior output reads vs vw writes

        // lane-cached columns (both float4 now)
        float ofr[NX], ltr[NX];
        #pragma unroll
        for (int k4 = 0; k4 < NX; k4 += 4) {
            const float4 v = *(const float4*)&offT_s[lane*VST + k4];  // off[i][lane]
            ofr[k4]=v.x; ofr[k4+1]=v.y; ofr[k4+2]=v.z; ofr[k4+3]=v.w;
            const float4 u = *(const float4*)&li_s[lane*VST + k4];    // Linv[k][lane]
            ltr[k4]=u.x; ltr[k4+1]=u.y; ltr[k4+2]=u.z; ltr[k4+3]=u.w;
        }

        // phase 1: tmp[m][lane] = g[m][lane] - sum_i vw[m][i]*off[i][lane]
        #pragma unroll
        for (int t = 0; t < 9; t++) {
            const int m = w + 8*t;
            if (m < 65) {
                float s = (m == 0) ? u_s[lane] : gcur[t];
                const float4* vp = (const float4*)&vw[m*VST];
                #pragma unroll
                for (int q = 0; q < 8; q++) {
                    const float4 v4 = vp[q];
                    s -= v4.x*ofr[4*q] + v4.y*ofr[4*q+1] + v4.z*ofr[4*q+2] + v4.w*ofr[4*q+3];
                }
                tmp[m*VST + lane] = s;
            }
        }
        __syncwarp();
        // phase 2: vw[m][lane] = sum_k tmp[m][k]*Linv[k][lane]
        #pragma unroll
        for (int t = 0; t < 9; t++) {
            const int m = w + 8*t;
            if (m < 65) {
                float s = 0.f;
                const float4* tp = (const float4*)&tmp[m*VST];
                #pragma unroll
                for (int q = 0; q < 8; q++) {
                    const float4 t4 = tp[q];
                    s += t4.x*ltr[4*q] + t4.y*ltr[4*q+1] + t4.z*ltr[4*q+2] + t4.w*ltr[4*q+3];
                }
                vw[m*VST + lane] = s;
            }
        }
        __syncthreads();   // B3: vw complete before cross-warp output read

        if (r <= rmainTop) {
            float* orow = out + (size_t)r * 2048;
            #pragma unroll
            for (int t = 0; t < 8; t++) {
                const int idx = tid + BNT*t;
                const int m = idx >> 5, i = idx & 31;
                orow[idx] = vw[i] + vw[(m+1)*VST + i];
            }
        }
    }
}

extern "C" void kernel_launch(void* const* d_in, const int* in_sizes, int n_in,
                              void* d_out, int out_size) {
    const float* hess  = (const float*)d_in[0];   // (8192,32,32)
    const float* grads = (const float*)d_in[1];   // (8192,1,32)
    const float* Amat  = (const float*)d_in[2];   // (32,32)
    const float* Ptp   = (const float*)d_in[3];   // (32,32)
    const float* Pinit = (const float*)d_in[4];   // (32,32)
    const float* epsx  = (const float*)d_in[5];   // (8192,64,32)
    float* out = (float*)d_out;                   // (8192,64,32)
    (void)in_sizes; (void)n_in; (void)out_size;

    fwd_kernel<<<FW_BLOCKS, 128>>>(hess, grads, Amat, Ptp, Pinit);
    prep_kernel<<<RR/PR_WPB, 256>>>();
    bwd_kernel<<<BW_BLOCKS, BNT>>>(epsx, out);
}